// round 7
// baseline (speedup 1.0000x reference)
#include <cuda_runtime.h>
#include <cuda_bf16.h>
#include <math.h>
#include <stdint.h>

// Problem constants
#define PB   4
#define PS   2048
#define PH   1024      // hidden = NH*HD
#define PNH  16
#define PHD  64
#define PWH  32        // window half = WIN//2
#define PM   (PB*PS)   // 8192 GEMM rows

// Scratch (allocation-free)
#define SCR_ELEMS (PB*PS*PH)
__device__ float g_q[SCR_ELEMS];
__device__ float g_k[SCR_ELEMS];
__device__ float g_v[SCR_ELEMS];
__device__ float g_a[SCR_ELEMS];   // attention out, stored tf32-rounded
__device__ float g_xr[SCR_ELEMS];  // x rounded to tf32
__device__ float g_wq[PH*PH];
__device__ float g_wk[PH*PH];
__device__ float g_wv[PH*PH];
__device__ float g_wo[PH*PH];

// ---------------------------------------------------------------------------
// TF32 helpers
// ---------------------------------------------------------------------------
__device__ __forceinline__ float to_tf32(float x) {
    uint32_t u;
    asm("cvt.rna.tf32.f32 %0, %1;" : "=r"(u) : "f"(x));
    return __uint_as_float(u);
}

__device__ __forceinline__ void mma_tf32(float* c, const float* a, const float* b) {
    asm volatile(
        "mma.sync.aligned.m16n8k8.row.col.f32.tf32.tf32.f32 "
        "{%0,%1,%2,%3}, {%4,%5,%6,%7}, {%8,%9}, {%0,%1,%2,%3};"
        : "+f"(c[0]), "+f"(c[1]), "+f"(c[2]), "+f"(c[3])
        : "r"(__float_as_uint(a[0])), "r"(__float_as_uint(a[1])),
          "r"(__float_as_uint(a[2])), "r"(__float_as_uint(a[3])),
          "r"(__float_as_uint(b[0])), "r"(__float_as_uint(b[1])));
}

__device__ __forceinline__ void cp16(void* smem_dst, const void* gmem_src) {
    uint32_t d = (uint32_t)__cvta_generic_to_shared(smem_dst);
    asm volatile("cp.async.ca.shared.global [%0], [%1], 16;\n"
                 :: "r"(d), "l"(gmem_src));
}

// ---------------------------------------------------------------------------
// Pre-pass: round fp32 -> tf32 (RN), element count multiple of 4
// ---------------------------------------------------------------------------
__global__ __launch_bounds__(256) void tf32_round_kernel(
    const float* __restrict__ in, float* __restrict__ out, int n4)
{
    int i = blockIdx.x * 256 + threadIdx.x;
    if (i < n4) {
        float4 v = ((const float4*)in)[i];
        v.x = to_tf32(v.x); v.y = to_tf32(v.y);
        v.z = to_tf32(v.z); v.w = to_tf32(v.w);
        ((float4*)out)[i] = v;
    }
}

// ---------------------------------------------------------------------------
// GEMM v2 (TF32, cp.async 2-stage double buffer). Operands pre-rounded.
// 128x128 block, BK=16, 8 warps (2m x 4n), warp tile 64x32, m16n8k8
// ---------------------------------------------------------------------------
#define GK 1024
#define GN 1024
#define BK 16
#define SA 20    // As row stride: (20g+tg)%32 bijective over warp -> no conflicts
#define SB 136   // Bs row stride: (8tg+g)%32 bijective -> no conflicts

__global__ __launch_bounds__(256) void gemm_tf32_db(
    const float* __restrict__ A, const float* __restrict__ W,
    const float* __restrict__ bias, float* __restrict__ C)
{
    __shared__ float As[2][128][SA];  // 2*128*20*4 = 20480 B
    __shared__ float Bs[2][BK][SB];   // 2*16*136*4 = 17408 B

    const int tid = threadIdx.x;
    const int m0 = blockIdx.y * 128;
    const int n0 = blockIdx.x * 128;
    const int warp = tid >> 5;
    const int lane = tid & 31;
    const int g  = lane >> 2;
    const int tg = lane & 3;
    const int wm = (warp & 1) * 64;
    const int wn = (warp >> 1) * 32;

    // copy decomposition (per stage: A 512 float4, B 512 float4; 2 each/thread)
    const int ar = tid >> 1;             // A row 0..127
    const int ac = (tid & 1) << 3;       // A col {0,8}; +0/+4 via two cp16
    const int br = tid >> 4;             // B row 0..15
    const int bc = (tid & 15) << 3;      // B col {0,8,...,120}; two cp16

    auto load_stage = [&](int s, int k0) {
        cp16(&As[s][ar][ac],     A + (size_t)(m0 + ar) * GK + k0 + ac);
        cp16(&As[s][ar][ac + 4], A + (size_t)(m0 + ar) * GK + k0 + ac + 4);
        cp16(&Bs[s][br][bc],     W + (size_t)(k0 + br) * GN + n0 + bc);
        cp16(&Bs[s][br][bc + 4], W + (size_t)(k0 + br) * GN + n0 + bc + 4);
        asm volatile("cp.async.commit_group;\n" ::: "memory");
    };

    float acc[4][4][4];
    #pragma unroll
    for (int mi = 0; mi < 4; mi++)
        #pragma unroll
        for (int ni = 0; ni < 4; ni++)
            #pragma unroll
            for (int r = 0; r < 4; r++) acc[mi][ni][r] = 0.f;

    load_stage(0, 0);

    constexpr int NIT = GK / BK;  // 64
    for (int it = 0; it < NIT; it++) {
        if (it + 1 < NIT) load_stage((it + 1) & 1, (it + 1) * BK);
        if (it + 1 < NIT)
            asm volatile("cp.async.wait_group 1;\n" ::: "memory");
        else
            asm volatile("cp.async.wait_group 0;\n" ::: "memory");
        __syncthreads();

        const int s = it & 1;
        #pragma unroll
        for (int ks = 0; ks < 2; ks++) {
            const int kb = ks * 8;
            float af[4][4], bf[4][2];
            #pragma unroll
            for (int mi = 0; mi < 4; mi++) {
                const int mr = wm + mi * 16 + g;
                af[mi][0] = As[s][mr    ][kb + tg];
                af[mi][1] = As[s][mr + 8][kb + tg];
                af[mi][2] = As[s][mr    ][kb + tg + 4];
                af[mi][3] = As[s][mr + 8][kb + tg + 4];
            }
            #pragma unroll
            for (int ni = 0; ni < 4; ni++) {
                const int nc = wn + ni * 8 + g;
                bf[ni][0] = Bs[s][kb + tg    ][nc];
                bf[ni][1] = Bs[s][kb + tg + 4][nc];
            }
            #pragma unroll
            for (int mi = 0; mi < 4; mi++)
                #pragma unroll
                for (int ni = 0; ni < 4; ni++)
                    mma_tf32(acc[mi][ni], af[mi], bf[ni]);
        }
        __syncthreads();
    }

    // Epilogue: bias + float2 stores (fp32)
    #pragma unroll
    for (int mi = 0; mi < 4; mi++) {
        const int row0 = m0 + wm + mi * 16 + g;
        #pragma unroll
        for (int ni = 0; ni < 4; ni++) {
            const int col = n0 + wn + ni * 8 + tg * 2;
            const float2 bv = *(const float2*)(bias + col);
            float2 o0, o1;
            o0.x = acc[mi][ni][0] + bv.x; o0.y = acc[mi][ni][1] + bv.y;
            o1.x = acc[mi][ni][2] + bv.x; o1.y = acc[mi][ni][3] + bv.y;
            *(float2*)(C + (size_t)row0 * GN + col)       = o0;
            *(float2*)(C + (size_t)(row0 + 8) * GN + col) = o1;
        }
    }
}

// ---------------------------------------------------------------------------
// Banded attention v2 (R6, 166us): warp owns 4 consecutive queries.
// Output stores are tf32-rounded so the O-projection GEMM needs no cvt.
// ---------------------------------------------------------------------------
#define KSTR 68

__global__ __launch_bounds__(256) void attn_kernel(
    const float* __restrict__ q, const float* __restrict__ k,
    const float* __restrict__ v, const int* __restrict__ mask,
    float* __restrict__ out)
{
    constexpr int QT = 32;
    constexpr int KT = QT + 2 * PWH;  // 96
    __shared__ float Ks[KT * KSTR];
    __shared__ float Qs[QT][PHD];
    __shared__ float Pr4[8][4][68];

    const int nqt = PS / QT;
    const int blk = blockIdx.x;
    const int qt = blk % nqt;
    const int h  = (blk / nqt) % PNH;
    const int b  = blk / (nqt * PNH);
    const int t0 = qt * QT;
    const int tid = threadIdx.x;
    const size_t base = ((size_t)b * PS) * PH + (size_t)h * PHD;

    for (int idx = tid; idx < KT * (PHD / 4); idx += 256) {
        int r  = idx >> 4;
        int c4 = (idx & 15) << 2;
        int jg = t0 - PWH + r;
        float4 kv = make_float4(0.f, 0.f, 0.f, 0.f);
        if (jg >= 0 && jg < PS)
            kv = *(const float4*)(k + base + (size_t)jg * PH + c4);
        *(float4*)(&Ks[r * KSTR + c4]) = kv;
    }
    for (int idx = tid; idx < QT * (PHD / 4); idx += 256) {
        int r  = idx >> 4;
        int c4 = (idx & 15) << 2;
        *(float4*)(&Qs[r][c4]) =
            *(const float4*)(q + base + (size_t)(t0 + r) * PH + c4);
    }
    __syncthreads();

    const int w = tid >> 5, l = tid & 31;
    const float inv_scale = 0.125f;

    #pragma unroll
    for (int qi = 0; qi < 4; qi++) {
        const int ql = 4 * w + qi;
        const int ig = t0 + ql;
        const int j0 = ig - PWH + l;
        const int j1 = j0 + 32;
        const int j2 = ig + PWH;
        const bool v0 = (j0 >= 0) && (j0 < PS) && (mask[b * PS + j0] != 0);
        const bool v1 = (j1 < PS) && (mask[b * PS + j1] != 0);
        const bool v2 = (j2 < PS) && (mask[b * PS + j2] != 0);

        const float4* K0 = (const float4*)(&Ks[(ql + l)      * KSTR]);
        const float4* K1 = (const float4*)(&Ks[(ql + l + 32) * KSTR]);
        const float4* K2 = (const float4*)(&Ks[(ql + 64)     * KSTR]);
        const float4* Qv = (const float4*)(&Qs[ql][0]);

        float s0 = 0.f, s1 = 0.f, s2 = 0.f;
        #pragma unroll
        for (int d4 = 0; d4 < PHD / 4; d4++) {
            float4 qv = Qv[d4];
            float4 a = K0[d4], c = K1[d4], e = K2[d4];
            s0 += qv.x * a.x + qv.y * a.y + qv.z * a.z + qv.w * a.w;
            s1 += qv.x * c.x + qv.y * c.y + qv.z * c.z + qv.w * c.w;
            s2 += qv.x * e.x + qv.y * e.y + qv.z * e.z + qv.w * e.w;
        }
        s0 = v0 ? s0 * inv_scale : -INFINITY;
        s1 = v1 ? s1 * inv_scale : -INFINITY;
        s2 = v2 ? s2 * inv_scale : -INFINITY;

        float m = fmaxf(fmaxf(s0, s1), s2);
        #pragma unroll
        for (int off = 16; off; off >>= 1)
            m = fmaxf(m, __shfl_xor_sync(0xffffffffu, m, off));

        const bool any = (m > -INFINITY);
        float e0 = (v0 && any) ? __expf(s0 - m) : 0.f;
        float e1 = (v1 && any) ? __expf(s1 - m) : 0.f;
        float e2 = (v2 && any) ? __expf(s2 - m) : 0.f;

        float ssum = e0 + e1;
        #pragma unroll
        for (int off = 16; off; off >>= 1)
            ssum += __shfl_xor_sync(0xffffffffu, ssum, off);
        ssum += e2;
        const float inv = any ? (1.0f / ssum) : 0.f;

        #pragma unroll
        for (int r = l; r < 68; r += 32) Pr4[w][qi][r] = 0.f;
        __syncwarp();
        Pr4[w][qi][qi + l]      = e0 * inv;
        Pr4[w][qi][qi + l + 32] = e1 * inv;
        if (l == 0) Pr4[w][qi][qi + 64] = e2 * inv;
        __syncwarp();
    }

    const int r0g = t0 + 4 * w - PWH;
    float2 a0 = make_float2(0.f, 0.f), a1 = a0, a2 = a0, a3 = a0;

    #pragma unroll 4
    for (int r = 0; r < 68; r++) {
        int jg = r0g + r;
        jg = min(max(jg, 0), PS - 1);
        const float2 vv = *(const float2*)(v + base + (size_t)jg * PH + 2 * l);
        const float p0 = Pr4[w][0][r];
        const float p1 = Pr4[w][1][r];
        const float p2 = Pr4[w][2][r];
        const float p3 = Pr4[w][3][r];
        a0.x += p0 * vv.x; a0.y += p0 * vv.y;
        a1.x += p1 * vv.x; a1.y += p1 * vv.y;
        a2.x += p2 * vv.x; a2.y += p2 * vv.y;
        a3.x += p3 * vv.x; a3.y += p3 * vv.y;
    }

    {
        const int ig0 = t0 + 4 * w;
        float* o = (float*)(out + base + (size_t)ig0 * PH + 2 * l);
        a0.x = to_tf32(a0.x); a0.y = to_tf32(a0.y);
        a1.x = to_tf32(a1.x); a1.y = to_tf32(a1.y);
        a2.x = to_tf32(a2.x); a2.y = to_tf32(a2.y);
        a3.x = to_tf32(a3.x); a3.y = to_tf32(a3.y);
        *(float2*)(o)          = a0;
        *(float2*)(o + PH)     = a1;
        *(float2*)(o + 2 * PH) = a2;
        *(float2*)(o + 3 * PH) = a3;
    }
}

// ---------------------------------------------------------------------------
extern "C" void kernel_launch(void* const* d_in, const int* in_sizes, int n_in,
                              void* d_out, int out_size)
{
    const float* x    = (const float*)d_in[0];
    const int*   mask = (const int*)  d_in[1];
    const float* Wq   = (const float*)d_in[2];
    const float* bq   = (const float*)d_in[3];
    const float* Wk   = (const float*)d_in[4];
    const float* bk   = (const float*)d_in[5];
    const float* Wv   = (const float*)d_in[6];
    const float* bv   = (const float*)d_in[7];
    const float* Wo   = (const float*)d_in[8];
    const float* bo   = (const float*)d_in[9];
    float* out = (float*)d_out;

    float *qp, *kp, *vp, *ap, *xr, *wq, *wk, *wv, *wo;
    cudaGetSymbolAddress((void**)&qp, g_q);
    cudaGetSymbolAddress((void**)&kp, g_k);
    cudaGetSymbolAddress((void**)&vp, g_v);
    cudaGetSymbolAddress((void**)&ap, g_a);
    cudaGetSymbolAddress((void**)&xr, g_xr);
    cudaGetSymbolAddress((void**)&wq, g_wq);
    cudaGetSymbolAddress((void**)&wk, g_wk);
    cudaGetSymbolAddress((void**)&wv, g_wv);
    cudaGetSymbolAddress((void**)&wo, g_wo);

    // Pre-round operands to tf32 (RN) so GEMMs run cvt-free cp.async copies
    const int nx4 = SCR_ELEMS / 4, nw4 = PH * PH / 4;
    tf32_round_kernel<<<(nx4 + 255) / 256, 256>>>(x,  xr, nx4);
    tf32_round_kernel<<<(nw4 + 255) / 256, 256>>>(Wq, wq, nw4);
    tf32_round_kernel<<<(nw4 + 255) / 256, 256>>>(Wk, wk, nw4);
    tf32_round_kernel<<<(nw4 + 255) / 256, 256>>>(Wv, wv, nw4);
    tf32_round_kernel<<<(nw4 + 255) / 256, 256>>>(Wo, wo, nw4);

    dim3 ggrid(GN / 128, PM / 128);  // (8, 64)
    gemm_tf32_db<<<ggrid, 256>>>(xr, wq, bq, qp);
    gemm_tf32_db<<<ggrid, 256>>>(xr, wk, bk, kp);
    gemm_tf32_db<<<ggrid, 256>>>(xr, wv, bv, vp);

    attn_kernel<<<PB * PNH * (PS / 32), 256>>>(qp, kp, vp, mask, ap);

    gemm_tf32_db<<<ggrid, 256>>>(ap, wo, bo, out);
}